// round 11
// baseline (speedup 1.0000x reference)
#include <cuda_runtime.h>
#include <cuda_fp16.h>
#include <cstdint>

#define D 128
#define MAXN 100000
#define MAXE 600000
#define SCAN_NB ((MAXN + 255) / 256)   // 391

// Scratch (device globals; no allocs allowed)
__device__ float  g_A[(size_t)MAXN * D];     // 51.2 MB
__device__ __half g_srcH[(size_t)MAXN * D];  // 25.6 MB fp16 src cache
__device__ int    g_count[MAXN];             // zeroed by scan each run
__device__ int    g_offs[MAXN];
__device__ int    g_state[SCAN_NB];          // lookback state; re-armed by permute
__device__ float2 g_meta[MAXE];              // (.x = src id bits, .y = w)

// ---------------------------------------------------------------------------
// Kernel 0: convert src_x -> fp16 cache  +  histogram of dst
// ---------------------------------------------------------------------------
__global__ void convert_hist_kernel(const float* __restrict__ src,
                                    const int* __restrict__ ei,
                                    int n8, int E) {
    int i = blockIdx.x * blockDim.x + threadIdx.x;
    if (i < n8) {
        float4 a = __ldg((const float4*)src + 2 * i);
        float4 b = __ldg((const float4*)src + 2 * i + 1);
        __half2 h0 = __floats2half2_rn(a.x, a.y);
        __half2 h1 = __floats2half2_rn(a.z, a.w);
        __half2 h2 = __floats2half2_rn(b.x, b.y);
        __half2 h3 = __floats2half2_rn(b.z, b.w);
        uint4 o;
        o.x = *(uint32_t*)&h0;
        o.y = *(uint32_t*)&h1;
        o.z = *(uint32_t*)&h2;
        o.w = *(uint32_t*)&h3;
        ((uint4*)g_srcH)[i] = o;
    }
    if (i < E) atomicAdd(&g_count[__ldg(&ei[E + i])], 1);
}

// ---------------------------------------------------------------------------
// Kernel 1: single-pass exclusive scan (decoupled lookback) — R9 verbatim
// ---------------------------------------------------------------------------
__global__ __launch_bounds__(256) void scan_kernel(int N) {
    __shared__ int ws[8];
    __shared__ int s_prefix;
    int tid = threadIdx.x, lane = tid & 31, wrp = tid >> 5;
    int b = blockIdx.x;
    int i = b * 256 + tid;
    int c = (i < N) ? g_count[i] : 0;
    if (i < N) g_count[i] = 0;

    int v = c;
#pragma unroll
    for (int o = 1; o < 32; o <<= 1) {
        int t = __shfl_up_sync(0xffffffffu, v, o);
        if (lane >= o) v += t;
    }
    if (lane == 31) ws[wrp] = v;
    __syncthreads();
    if (wrp == 0) {
        int s = (lane < 8) ? ws[lane] : 0;
#pragma unroll
        for (int o = 1; o < 8; o <<= 1) {
            int t = __shfl_up_sync(0xffffffffu, s, o);
            if (lane >= o) s += t;
        }
        if (lane < 8) ws[lane] = s;
    }
    __syncthreads();
    int incl = v + ((wrp > 0) ? ws[wrp - 1] : 0);
    int total = ws[7];

    if (tid == 0) {
        __threadfence();
        if (b == 0) {
            atomicExch(&g_state[0], (2 << 24) | total);
            s_prefix = 0;
        } else {
            atomicExch(&g_state[b], (1 << 24) | total);
        }
    }

    if (b > 0 && wrp == 0) {
        int agg = 0;
        int p_hi = b - 1;
        while (true) {
            int p = p_hi - lane;
            int st = (p >= 0) ? atomicAdd(&g_state[p], 0) : (2 << 24);
            int flag = st >> 24;
            int val = st & 0xFFFFFF;
            unsigned m2 = __ballot_sync(0xffffffffu, flag == 2);
            unsigned m0 = __ballot_sync(0xffffffffu, flag == 0);
            if (m2) {
                int k = __ffs(m2) - 1;
                if (m0 & ((1u << k) - 1)) continue;
                int vv = (lane <= k) ? val : 0;
#pragma unroll
                for (int o = 16; o; o >>= 1) vv += __shfl_down_sync(0xffffffffu, vv, o);
                vv = __shfl_sync(0xffffffffu, vv, 0);
                agg += vv;
                break;
            } else {
                if (m0) continue;
                int vv = val;
#pragma unroll
                for (int o = 16; o; o >>= 1) vv += __shfl_down_sync(0xffffffffu, vv, o);
                vv = __shfl_sync(0xffffffffu, vv, 0);
                agg += vv;
                p_hi -= 32;
            }
        }
        if (lane == 0) {
            s_prefix = agg;
            __threadfence();
            atomicExch(&g_state[b], (2 << 24) | (agg + total));
        }
    }
    __syncthreads();
    if (i < N) g_offs[i] = s_prefix + incl - c;
}

// ---------------------------------------------------------------------------
// Kernel 2: permute (advances g_offs in place; re-arms g_state)
// ---------------------------------------------------------------------------
__global__ void permute_kernel(const int* __restrict__ ei,
                               const float* __restrict__ ew, int E, int nb) {
    int e = blockIdx.x * blockDim.x + threadIdx.x;
    if (e < nb) g_state[e] = 0;
    if (e < E) {
        int dst = ei[E + e];
        int src = ei[e];
        float w = ew[e];
        int pos = atomicAdd(&g_offs[dst], 1);
        g_meta[pos] = make_float2(__int_as_float(src), w);
    }
}

// ---------------------------------------------------------------------------
// Kernel 3: gather (fp16 rows) — R9 verbatim
// ---------------------------------------------------------------------------
__global__ __launch_bounds__(256) void gather_kernel(int N) {
    int w = (blockIdx.x * 256 + threadIdx.x) >> 5;
    int lane = threadIdx.x & 31;
    if (w >= N) return;
    int end = __ldg(&g_offs[w]);
    int base = (w > 0) ? __ldg(&g_offs[w - 1]) : 0;
    int deg = end - base;
    float4 acc = make_float4(0.f, 0.f, 0.f, 0.f);

    for (int c0 = 0; c0 < deg; c0 += 32) {
        int cn = min(deg - c0, 32);
        float2 mv = make_float2(0.f, 0.f);
        if (lane < cn) mv = __ldg(&g_meta[base + c0 + lane]);
        for (int j = 0; j < cn; j += 4) {
            uint2 h[4];
            float wv[4];
#pragma unroll
            for (int u = 0; u < 4; ++u) {
                int idx = j + u;
                int su = __shfl_sync(0xffffffffu, __float_as_int(mv.x), idx & 31);
                float wu = __shfl_sync(0xffffffffu, mv.y, idx & 31);
                bool valid = idx < cn;
                wv[u] = valid ? wu : 0.f;
                if (valid)
                    h[u] = __ldg((const uint2*)(g_srcH + (size_t)su * D) + lane);
                else
                    h[u] = make_uint2(0u, 0u);
            }
#pragma unroll
            for (int u = 0; u < 4; ++u) {
                float2 f01 = __half22float2(*(__half2*)&h[u].x);
                float2 f23 = __half22float2(*(__half2*)&h[u].y);
                acc.x += wv[u] * f01.x;
                acc.y += wv[u] * f01.y;
                acc.z += wv[u] * f23.x;
                acc.w += wv[u] * f23.y;
            }
        }
    }
    ((float4*)(g_A + (size_t)w * D))[lane] = acc;
}

// ---------------------------------------------------------------------------
// Kernel 4: fused dual GEMM + leaky_relu (tf32 mma.sync), optimized:
//  - Wi/Wn held in smem for the FULL K (filled once, 139KB) — no per-tile W fill
//  - u/v tiles double-buffered; d/a staged in 16 regs so LDG(kt+1) overlaps
//    the HMMA block of tile kt. One __syncthreads per k-tile.
//   out = leaky_relu( (dst_x + A) @ Wi^T + (dst_x * A) @ Wn^T )
// ---------------------------------------------------------------------------
#define SSTR 136
// dynamic smem word layout:
//   u_f : [2][16][SSTR]            (8704 words)
//   v_f : [2][16][SSTR]            (8704 words)
//   wi_f: [128][SSTR]              (17408 words)
//   wn_f: [128][SSTR]              (17408 words)
#define GEMM_SMEM_WORDS (2 * 16 * SSTR * 2 + 128 * SSTR * 2)
#define GEMM_SMEM_BYTES (GEMM_SMEM_WORDS * 4)

__device__ __forceinline__ uint32_t f2tf32(float x) {
    uint32_t r;
    asm("cvt.rna.tf32.f32 %0, %1;" : "=r"(r) : "f"(x));
    return r;
}

__device__ __forceinline__ void mma_tf32(float c[4], const uint32_t a[4],
                                         const uint32_t b[2]) {
    asm volatile(
        "mma.sync.aligned.m16n8k8.row.col.f32.tf32.tf32.f32 "
        "{%0,%1,%2,%3},{%4,%5,%6,%7},{%8,%9},{%0,%1,%2,%3};"
        : "+f"(c[0]), "+f"(c[1]), "+f"(c[2]), "+f"(c[3])
        : "r"(a[0]), "r"(a[1]), "r"(a[2]), "r"(a[3]), "r"(b[0]), "r"(b[1]));
}

__global__ __launch_bounds__(256) void fused_gemm_tc_kernel(
    const float* __restrict__ dstx,
    const float* __restrict__ Wi,
    const float* __restrict__ Wn,
    float* __restrict__ out, int N) {

    extern __shared__ uint32_t sm[];
    uint32_t* u_f = sm;                         // [2][16][SSTR]
    uint32_t* v_f = sm + 2 * 16 * SSTR;         // [2][16][SSTR]
    uint32_t* wi_f = sm + 4 * 16 * SSTR;        // [128][SSTR]
    uint32_t* wn_f = wi_f + 128 * SSTR;         // [128][SSTR]

    const int tid = threadIdx.x;
    const int lane = tid & 31;
    const int wid = tid >> 5;
    const int wm = wid >> 2;     // 0..1
    const int wn = wid & 3;      // 0..3
    const int grp = lane >> 2;   // 0..7
    const int qid = lane & 3;    // 0..3
    const int row0 = blockIdx.x * 128;

    const int fm = tid >> 1;          // 0..127
    const int fkq = (tid & 1) * 8;    // 0 or 8
    const int frow = row0 + fm;
    const bool frow_ok = frow < N;

    // ---- one-time W fill: full K=128, k-major, conflict-free STS (R3 pattern)
#pragma unroll
    for (int kt = 0; kt < 8; ++kt) {
        const int kg = kt * 16 + fkq;
        const float4* wip = (const float4*)(Wi + fm * D + kg);
        const float4* wnp = (const float4*)(Wn + fm * D + kg);
        float4 wi0 = __ldg(wip), wi1 = __ldg(wip + 1);
        float4 wn0 = __ldg(wnp), wn1 = __ldg(wnp + 1);
        float wif[8] = {wi0.x, wi0.y, wi0.z, wi0.w, wi1.x, wi1.y, wi1.z, wi1.w};
        float wnf[8] = {wn0.x, wn0.y, wn0.z, wn0.w, wn1.x, wn1.y, wn1.z, wn1.w};
#pragma unroll
        for (int j = 0; j < 8; ++j) {
            wi_f[(kg + j) * SSTR + fm] = f2tf32(wif[j]);
            wn_f[(kg + j) * SSTR + fm] = f2tf32(wnf[j]);
        }
    }

    float acc[4][4][4];
#pragma unroll
    for (int mt = 0; mt < 4; ++mt)
#pragma unroll
        for (int nt = 0; nt < 4; ++nt)
#pragma unroll
            for (int c = 0; c < 4; ++c) acc[mt][nt][c] = 0.f;

    // ---- prologue: stage + store tile 0 into buffer 0
    float4 d0 = make_float4(0.f, 0.f, 0.f, 0.f), d1 = d0, a0 = d0, a1 = d0;
    if (frow_ok) {
        const float4* dp = (const float4*)(dstx + (size_t)frow * D + fkq);
        const float4* ap = (const float4*)(g_A + (size_t)frow * D + fkq);
        d0 = __ldg(dp); d1 = __ldg(dp + 1);
        a0 = __ldg(ap); a1 = __ldg(ap + 1);
    }
    {
        float du[8] = {d0.x, d0.y, d0.z, d0.w, d1.x, d1.y, d1.z, d1.w};
        float au[8] = {a0.x, a0.y, a0.z, a0.w, a1.x, a1.y, a1.z, a1.w};
#pragma unroll
        for (int j = 0; j < 8; ++j) {
            u_f[(fkq + j) * SSTR + fm] = f2tf32(du[j] + au[j]);
            v_f[(fkq + j) * SSTR + fm] = f2tf32(du[j] * au[j]);
        }
    }

    for (int kt = 0; kt < 8; ++kt) {
        __syncthreads();   // buffer (kt&1) filled; buffer ((kt+1)&1) free

        // ---- issue next tile's LDGs (latency hidden under this tile's mma)
        if (kt < 7) {
            const int kg = (kt + 1) * 16 + fkq;
            d0 = make_float4(0.f, 0.f, 0.f, 0.f); d1 = d0; a0 = d0; a1 = d0;
            if (frow_ok) {
                const float4* dp = (const float4*)(dstx + (size_t)frow * D + kg);
                const float4* ap = (const float4*)(g_A + (size_t)frow * D + kg);
                d0 = __ldg(dp); d1 = __ldg(dp + 1);
                a0 = __ldg(ap); a1 = __ldg(ap + 1);
            }
        }

        // ---- mma on buffer kt&1; W indexed by global k
        const uint32_t* ub = u_f + (kt & 1) * 16 * SSTR;
        const uint32_t* vb = v_f + (kt & 1) * 16 * SSTR;
        const int k0 = kt * 16;
#pragma unroll
        for (int ph = 0; ph < 2; ++ph) {
            const uint32_t* S = ph ? vb : ub;
            const uint32_t* W = ph ? wn_f : wi_f;
#pragma unroll
            for (int kk = 0; kk < 16; kk += 8) {
                uint32_t af[4][4];
#pragma unroll
                for (int mt = 0; mt < 4; ++mt) {
                    int mr = wm * 64 + mt * 16 + grp;
                    af[mt][0] = S[(kk + qid) * SSTR + mr];
                    af[mt][1] = S[(kk + qid) * SSTR + mr + 8];
                    af[mt][2] = S[(kk + qid + 4) * SSTR + mr];
                    af[mt][3] = S[(kk + qid + 4) * SSTR + mr + 8];
                }
                uint32_t bf[4][2];
#pragma unroll
                for (int nt = 0; nt < 4; ++nt) {
                    int nc = wn * 32 + nt * 8 + grp;
                    bf[nt][0] = W[(k0 + kk + qid) * SSTR + nc];
                    bf[nt][1] = W[(k0 + kk + qid + 4) * SSTR + nc];
                }
#pragma unroll
                for (int mt = 0; mt < 4; ++mt)
#pragma unroll
                    for (int nt = 0; nt < 4; ++nt)
                        mma_tf32(acc[mt][nt], af[mt], bf[nt]);
            }
        }

        // ---- store staged tile kt+1 into the other buffer (no sync needed:
        //      all warps finished reading it in iteration kt-1, fenced by the
        //      sync at the top of this iteration)
        if (kt < 7) {
            uint32_t* un = u_f + ((kt + 1) & 1) * 16 * SSTR;
            uint32_t* vn = v_f + ((kt + 1) & 1) * 16 * SSTR;
            float du[8] = {d0.x, d0.y, d0.z, d0.w, d1.x, d1.y, d1.z, d1.w};
            float au[8] = {a0.x, a0.y, a0.z, a0.w, a1.x, a1.y, a1.z, a1.w};
#pragma unroll
            for (int j = 0; j < 8; ++j) {
                un[(fkq + j) * SSTR + fm] = f2tf32(du[j] + au[j]);
                vn[(fkq + j) * SSTR + fm] = f2tf32(du[j] * au[j]);
            }
        }
    }

    // ---- epilogue: leaky_relu + float2 stores
#pragma unroll
    for (int mt = 0; mt < 4; ++mt) {
#pragma unroll
        for (int nt = 0; nt < 4; ++nt) {
            int col = wn * 32 + nt * 8 + qid * 2;
            int r0 = row0 + wm * 64 + mt * 16 + grp;
            int r1 = r0 + 8;
            float x0 = acc[mt][nt][0], x1 = acc[mt][nt][1];
            float x2 = acc[mt][nt][2], x3 = acc[mt][nt][3];
            x0 = x0 > 0.f ? x0 : 0.01f * x0;
            x1 = x1 > 0.f ? x1 : 0.01f * x1;
            x2 = x2 > 0.f ? x2 : 0.01f * x2;
            x3 = x3 > 0.f ? x3 : 0.01f * x3;
            if (r0 < N)
                *(float2*)(out + (size_t)r0 * D + col) = make_float2(x0, x1);
            if (r1 < N)
                *(float2*)(out + (size_t)r1 * D + col) = make_float2(x2, x3);
        }
    }
}

// ---------------------------------------------------------------------------
extern "C" void kernel_launch(void* const* d_in, const int* in_sizes, int n_in,
                              void* d_out, int out_size) {
    const float* src_x = (const float*)d_in[0];
    const float* dst_x = (const float*)d_in[1];
    const int*   ei    = (const int*)d_in[2];    // [2, E]
    const float* ew    = (const float*)d_in[3];  // [E]
    const float* Wi    = (const float*)d_in[4];
    const float* Wn    = (const float*)d_in[5];
    float* out = (float*)d_out;

    int N = in_sizes[0] / D;
    int E = in_sizes[2] / 2;
    int nb = (N + 255) / 256;
    int n8 = N * (D / 8);
    int gmax = (n8 > E) ? n8 : E;

    cudaFuncSetAttribute(fused_gemm_tc_kernel,
                         cudaFuncAttributeMaxDynamicSharedMemorySize,
                         GEMM_SMEM_BYTES);

    convert_hist_kernel<<<(gmax + 255) / 256, 256>>>(src_x, ei, n8, E);
    scan_kernel<<<nb, 256>>>(N);
    permute_kernel<<<(E + 255) / 256, 256>>>(ei, ew, E, nb);
    gather_kernel<<<(N * 32 + 255) / 256, 256>>>(N);
    fused_gemm_tc_kernel<<<(N + 127) / 128, 256, GEMM_SMEM_BYTES>>>(
        dst_x, Wi, Wn, out, N);
}

// round 12
// speedup vs baseline: 1.2390x; 1.2390x over previous
#include <cuda_runtime.h>
#include <cuda_fp16.h>
#include <cstdint>

#define D 128
#define MAXN 100000
#define MAXE 600000
#define SCAN_NB ((MAXN + 255) / 256)   // 391

// Scratch (device globals; no allocs allowed)
__device__ float  g_A[(size_t)MAXN * D];     // 51.2 MB
__device__ __half g_srcH[(size_t)MAXN * D];  // 25.6 MB fp16 src cache
__device__ int    g_count[MAXN];             // zeroed by scan each run
__device__ int    g_offs[MAXN];
__device__ int    g_state[SCAN_NB];          // lookback state; re-armed by permute
__device__ float2 g_meta[MAXE];              // (.x = src id bits, .y = w)

// ---------------------------------------------------------------------------
// Kernel 0: convert src_x -> fp16 cache  +  histogram of dst
// ---------------------------------------------------------------------------
__global__ void convert_hist_kernel(const float* __restrict__ src,
                                    const int* __restrict__ ei,
                                    int n8, int E) {
    int i = blockIdx.x * blockDim.x + threadIdx.x;
    if (i < n8) {
        float4 a = __ldg((const float4*)src + 2 * i);
        float4 b = __ldg((const float4*)src + 2 * i + 1);
        __half2 h0 = __floats2half2_rn(a.x, a.y);
        __half2 h1 = __floats2half2_rn(a.z, a.w);
        __half2 h2 = __floats2half2_rn(b.x, b.y);
        __half2 h3 = __floats2half2_rn(b.z, b.w);
        uint4 o;
        o.x = *(uint32_t*)&h0;
        o.y = *(uint32_t*)&h1;
        o.z = *(uint32_t*)&h2;
        o.w = *(uint32_t*)&h3;
        ((uint4*)g_srcH)[i] = o;
    }
    if (i < E) atomicAdd(&g_count[__ldg(&ei[E + i])], 1);
}

// ---------------------------------------------------------------------------
// Kernel 1: single-pass exclusive scan (decoupled lookback) — R9 verbatim
// ---------------------------------------------------------------------------
__global__ __launch_bounds__(256) void scan_kernel(int N) {
    __shared__ int ws[8];
    __shared__ int s_prefix;
    int tid = threadIdx.x, lane = tid & 31, wrp = tid >> 5;
    int b = blockIdx.x;
    int i = b * 256 + tid;
    int c = (i < N) ? g_count[i] : 0;
    if (i < N) g_count[i] = 0;

    int v = c;
#pragma unroll
    for (int o = 1; o < 32; o <<= 1) {
        int t = __shfl_up_sync(0xffffffffu, v, o);
        if (lane >= o) v += t;
    }
    if (lane == 31) ws[wrp] = v;
    __syncthreads();
    if (wrp == 0) {
        int s = (lane < 8) ? ws[lane] : 0;
#pragma unroll
        for (int o = 1; o < 8; o <<= 1) {
            int t = __shfl_up_sync(0xffffffffu, s, o);
            if (lane >= o) s += t;
        }
        if (lane < 8) ws[lane] = s;
    }
    __syncthreads();
    int incl = v + ((wrp > 0) ? ws[wrp - 1] : 0);
    int total = ws[7];

    if (tid == 0) {
        __threadfence();
        if (b == 0) {
            atomicExch(&g_state[0], (2 << 24) | total);
            s_prefix = 0;
        } else {
            atomicExch(&g_state[b], (1 << 24) | total);
        }
    }

    if (b > 0 && wrp == 0) {
        int agg = 0;
        int p_hi = b - 1;
        while (true) {
            int p = p_hi - lane;
            int st = (p >= 0) ? atomicAdd(&g_state[p], 0) : (2 << 24);
            int flag = st >> 24;
            int val = st & 0xFFFFFF;
            unsigned m2 = __ballot_sync(0xffffffffu, flag == 2);
            unsigned m0 = __ballot_sync(0xffffffffu, flag == 0);
            if (m2) {
                int k = __ffs(m2) - 1;
                if (m0 & ((1u << k) - 1)) continue;
                int vv = (lane <= k) ? val : 0;
#pragma unroll
                for (int o = 16; o; o >>= 1) vv += __shfl_down_sync(0xffffffffu, vv, o);
                vv = __shfl_sync(0xffffffffu, vv, 0);
                agg += vv;
                break;
            } else {
                if (m0) continue;
                int vv = val;
#pragma unroll
                for (int o = 16; o; o >>= 1) vv += __shfl_down_sync(0xffffffffu, vv, o);
                vv = __shfl_sync(0xffffffffu, vv, 0);
                agg += vv;
                p_hi -= 32;
            }
        }
        if (lane == 0) {
            s_prefix = agg;
            __threadfence();
            atomicExch(&g_state[b], (2 << 24) | (agg + total));
        }
    }
    __syncthreads();
    if (i < N) g_offs[i] = s_prefix + incl - c;
}

// ---------------------------------------------------------------------------
// Kernel 2: permute (advances g_offs in place; re-arms g_state)
// ---------------------------------------------------------------------------
__global__ void permute_kernel(const int* __restrict__ ei,
                               const float* __restrict__ ew, int E, int nb) {
    int e = blockIdx.x * blockDim.x + threadIdx.x;
    if (e < nb) g_state[e] = 0;
    if (e < E) {
        int dst = ei[E + e];
        int src = ei[e];
        float w = ew[e];
        int pos = atomicAdd(&g_offs[dst], 1);
        g_meta[pos] = make_float2(__int_as_float(src), w);
    }
}

// ---------------------------------------------------------------------------
// Kernel 3: gather (fp16 rows) — R9 verbatim
// ---------------------------------------------------------------------------
__global__ __launch_bounds__(256) void gather_kernel(int N) {
    int w = (blockIdx.x * 256 + threadIdx.x) >> 5;
    int lane = threadIdx.x & 31;
    if (w >= N) return;
    int end = __ldg(&g_offs[w]);
    int base = (w > 0) ? __ldg(&g_offs[w - 1]) : 0;
    int deg = end - base;
    float4 acc = make_float4(0.f, 0.f, 0.f, 0.f);

    for (int c0 = 0; c0 < deg; c0 += 32) {
        int cn = min(deg - c0, 32);
        float2 mv = make_float2(0.f, 0.f);
        if (lane < cn) mv = __ldg(&g_meta[base + c0 + lane]);
        for (int j = 0; j < cn; j += 4) {
            uint2 h[4];
            float wv[4];
#pragma unroll
            for (int u = 0; u < 4; ++u) {
                int idx = j + u;
                int su = __shfl_sync(0xffffffffu, __float_as_int(mv.x), idx & 31);
                float wu = __shfl_sync(0xffffffffu, mv.y, idx & 31);
                bool valid = idx < cn;
                wv[u] = valid ? wu : 0.f;
                if (valid)
                    h[u] = __ldg((const uint2*)(g_srcH + (size_t)su * D) + lane);
                else
                    h[u] = make_uint2(0u, 0u);
            }
#pragma unroll
            for (int u = 0; u < 4; ++u) {
                float2 f01 = __half22float2(*(__half2*)&h[u].x);
                float2 f23 = __half22float2(*(__half2*)&h[u].y);
                acc.x += wv[u] * f01.x;
                acc.y += wv[u] * f01.y;
                acc.z += wv[u] * f23.x;
                acc.w += wv[u] * f23.y;
            }
        }
    }
    ((float4*)(g_A + (size_t)w * D))[lane] = acc;
}

// ---------------------------------------------------------------------------
// Kernel 4: fused dual GEMM + leaky_relu, fp16 mma.m16n8k16 (fp32 accum).
//   out = leaky_relu( (dst_x + A) @ Wi^T + (dst_x * A) @ Wn^T )
// Same R3 structure; smem words are half2 (k-pairs), K=32 per tile, 4 tiles.
// fp16 mantissa == tf32 mantissa (10 bits) -> same rounding as tf32 path.
// ---------------------------------------------------------------------------
#define SSTR 136

__device__ __forceinline__ uint32_t pkh2(float x, float y) {
    __half2 h = __floats2half2_rn(x, y);
    return *(uint32_t*)&h;
}

__device__ __forceinline__ void mma_f16(float c[4], const uint32_t a[4],
                                        const uint32_t b[2]) {
    asm volatile(
        "mma.sync.aligned.m16n8k16.row.col.f32.f16.f16.f32 "
        "{%0,%1,%2,%3},{%4,%5,%6,%7},{%8,%9},{%0,%1,%2,%3};"
        : "+f"(c[0]), "+f"(c[1]), "+f"(c[2]), "+f"(c[3])
        : "r"(a[0]), "r"(a[1]), "r"(a[2]), "r"(a[3]), "r"(b[0]), "r"(b[1]));
}

__global__ __launch_bounds__(256) void fused_gemm_tc_kernel(
    const float* __restrict__ dstx,
    const float* __restrict__ Wi,
    const float* __restrict__ Wn,
    float* __restrict__ out, int N) {

    // [kp][row] half2 words; 16 kp-rows (=32 k) per tile
    __shared__ uint32_t u_s[16][SSTR];
    __shared__ uint32_t v_s[16][SSTR];
    __shared__ uint32_t wi_s[16][SSTR];
    __shared__ uint32_t wn_s[16][SSTR];

    const int tid = threadIdx.x;
    const int lane = tid & 31;
    const int wid = tid >> 5;
    const int wm = wid >> 2;     // 0..1
    const int wn = wid & 3;      // 0..3
    const int grp = lane >> 2;   // 0..7
    const int qid = lane & 3;    // 0..3
    const int row0 = blockIdx.x * 128;

    const int fm = tid >> 1;          // 0..127 (node row / W out-row)
    const int fkq = (tid & 1) * 8;    // kp offset: 0 or 8 (element offset 0/16)
    const int frow = row0 + fm;
    const bool frow_ok = frow < N;

    float acc[4][4][4];
#pragma unroll
    for (int mt = 0; mt < 4; ++mt)
#pragma unroll
        for (int nt = 0; nt < 4; ++nt)
#pragma unroll
            for (int c = 0; c < 4; ++c) acc[mt][nt][c] = 0.f;

    for (int kt = 0; kt < 4; ++kt) {
        const int k0 = kt * 32 + fkq * 2;   // element offset of this thread's 16 floats
        // ---- fill: 16 floats each of d, a, Wi, Wn (4x LDG.128 each)
        {
            float du[16], au[16];
            if (frow_ok) {
                const float4* dp = (const float4*)(dstx + (size_t)frow * D + k0);
                const float4* ap = (const float4*)(g_A + (size_t)frow * D + k0);
#pragma unroll
                for (int q = 0; q < 4; ++q) {
                    float4 dv = __ldg(dp + q);
                    float4 av = __ldg(ap + q);
                    du[q * 4 + 0] = dv.x; du[q * 4 + 1] = dv.y;
                    du[q * 4 + 2] = dv.z; du[q * 4 + 3] = dv.w;
                    au[q * 4 + 0] = av.x; au[q * 4 + 1] = av.y;
                    au[q * 4 + 2] = av.z; au[q * 4 + 3] = av.w;
                }
            } else {
#pragma unroll
                for (int q = 0; q < 16; ++q) { du[q] = 0.f; au[q] = 0.f; }
            }
#pragma unroll
            for (int j = 0; j < 8; ++j) {
                u_s[fkq + j][fm] = pkh2(du[2 * j] + au[2 * j],
                                        du[2 * j + 1] + au[2 * j + 1]);
                v_s[fkq + j][fm] = pkh2(du[2 * j] * au[2 * j],
                                        du[2 * j + 1] * au[2 * j + 1]);
            }
            const float4* wip = (const float4*)(Wi + fm * D + k0);
            const float4* wnp = (const float4*)(Wn + fm * D + k0);
            float wif[16], wnf[16];
#pragma unroll
            for (int q = 0; q < 4; ++q) {
                float4 a = __ldg(wip + q);
                float4 b = __ldg(wnp + q);
                wif[q * 4 + 0] = a.x; wif[q * 4 + 1] = a.y;
                wif[q * 4 + 2] = a.z; wif[q * 4 + 3] = a.w;
                wnf[q * 4 + 0] = b.x; wnf[q * 4 + 1] = b.y;
                wnf[q * 4 + 2] = b.z; wnf[q * 4 + 3] = b.w;
            }
#pragma unroll
            for (int j = 0; j < 8; ++j) {
                wi_s[fkq + j][fm] = pkh2(wif[2 * j], wif[2 * j + 1]);
                wn_s[fkq + j][fm] = pkh2(wnf[2 * j], wnf[2 * j + 1]);
            }
        }
        __syncthreads();

        // ---- mma: 2 phases x 2 k16-steps x 4x4 tiles
#pragma unroll
        for (int ph = 0; ph < 2; ++ph) {
            const uint32_t(*S)[SSTR] = ph ? v_s : u_s;
            const uint32_t(*W)[SSTR] = ph ? wn_s : wi_s;
#pragma unroll
            for (int kk = 0; kk < 16; kk += 8) {
                uint32_t af[4][4];
#pragma unroll
                for (int mt = 0; mt < 4; ++mt) {
                    int mr = wm * 64 + mt * 16 + grp;
                    af[mt][0] = S[kk + qid][mr];
                    af[mt][1] = S[kk + qid][mr + 8];
                    af[mt][2] = S[kk + qid + 4][mr];
                    af[mt][3] = S[kk + qid + 4][mr + 8];
                }
                uint32_t bf[4][2];
#pragma unroll
                for (int nt = 0; nt < 4; ++nt) {
                    int nc = wn * 32 + nt * 8 + grp;
                    bf[nt][0] = W[kk + qid][nc];
                    bf[nt][1] = W[kk + qid + 4][nc];
                }
#pragma unroll
                for (int mt = 0; mt < 4; ++mt)
#pragma unroll
                    for (int nt = 0; nt < 4; ++nt)
                        mma_f16(acc[mt][nt], af[mt], bf[nt]);
            }
        }
        __syncthreads();
    }

    // ---- epilogue: leaky_relu + float2 stores
#pragma unroll
    for (int mt = 0; mt < 4; ++mt) {
#pragma unroll
        for (int nt = 0; nt < 4; ++nt) {
            int col = wn * 32 + nt * 8 + qid * 2;
            int r0 = row0 + wm * 64 + mt * 16 + grp;
            int r1 = r0 + 8;
            float x0 = acc[mt][nt][0], x1 = acc[mt][nt][1];
            float x2 = acc[mt][nt][2], x3 = acc[mt][nt][3];
            x0 = x0 > 0.f ? x0 : 0.01f * x0;
            x1 = x1 > 0.f ? x1 : 0.01f * x1;
            x2 = x2 > 0.f ? x2 : 0.01f * x2;
            x3 = x3 > 0.f ? x3 : 0.01f * x3;
            if (r0 < N)
                *(float2*)(out + (size_t)r0 * D + col) = make_float2(x0, x1);
            if (r1 < N)
                *(float2*)(out + (size_t)r1 * D + col) = make_float2(x2, x3);
        }
    }
}

// ---------------------------------------------------------------------------
extern "C" void kernel_launch(void* const* d_in, const int* in_sizes, int n_in,
                              void* d_out, int out_size) {
    const float* src_x = (const float*)d_in[0];
    const float* dst_x = (const float*)d_in[1];
    const int*   ei    = (const int*)d_in[2];    // [2, E]
    const float* ew    = (const float*)d_in[3];  // [E]
    const float* Wi    = (const float*)d_in[4];
    const float* Wn    = (const float*)d_in[5];
    float* out = (float*)d_out;

    int N = in_sizes[0] / D;
    int E = in_sizes[2] / 2;
    int nb = (N + 255) / 256;
    int n8 = N * (D / 8);
    int gmax = (n8 > E) ? n8 : E;

    convert_hist_kernel<<<(gmax + 255) / 256, 256>>>(src_x, ei, n8, E);
    scan_kernel<<<nb, 256>>>(N);
    permute_kernel<<<(E + 255) / 256, 256>>>(ei, ew, E, nb);
    gather_kernel<<<(N * 32 + 255) / 256, 256>>>(N);
    fused_gemm_tc_kernel<<<(N + 127) / 128, 256>>>(dst_x, Wi, Wn, out, N);
}